// round 13
// baseline (speedup 1.0000x reference)
#include <cuda_runtime.h>
#include <cuda_bf16.h>
#include <cstdint>
#include <stdint.h>
#include <math.h>

#define Bb 64
#define Hh 512
#define Gg 2048
#define Vv 32000
#define Tt 24

#define NVT 250                 // v tiles of 128
#define NKC 16                  // k chunks of 32
#define WSTEP 24576             // bytes per (tile,kchunk): 3 splits x 128 v x 32 k x 2B
#define HSTEP 12288             // bytes per kchunk: 3 splits x 64 b x 32 k x 2B
#define PITCH 80                // smem row pitch bytes (32 bf16 data + 8 pad)
#define WREG  30720             // 3 * 128 * 80
#define HREG  15360             // 3 * 64 * 80
#define STAGE 46080             // WREG + HREG
#define DPITCH 132              // epilogue smem pitch (floats)

// -------- scratch (static device globals; no allocation) --------
__device__ __nv_bfloat16 g_Wsplit[(size_t)NVT*NKC*(WSTEP/2)];  // 98.3 MB
__device__ __nv_bfloat16 g_Hsplit[NKC*(HSTEP/2)];              // 196 KB
__device__ float g_WhhT[Hh*Gg];
__device__ float g_hT[2][Hh*Bb];
__device__ float g_c[Bb*Hh];
__device__ float g_xv[Gg];
__device__ unsigned long long g_amax[Tt*Bb];
__device__ float g_mask[Bb];
__device__ int   g_x0nz;

__device__ __forceinline__ unsigned fkey(float f){
    unsigned u = __float_as_uint(f);
    return (u & 0x80000000u) ? ~u : (u | 0x80000000u);
}
__device__ __forceinline__ int dekey(unsigned long long key){
    return (int)(0xFFFFFFFFu - (unsigned)(key & 0xFFFFFFFFull));
}
__device__ __forceinline__ void cp16(unsigned d, const void* s){
    asm volatile("cp.async.cg.shared.global [%0], [%1], 16;" :: "r"(d), "l"(s));
}
#define CP_COMMIT() asm volatile("cp.async.commit_group;")
#define CP_WAIT1()  asm volatile("cp.async.wait_group 1;")
__device__ __forceinline__ unsigned smem_u32(const void* p){
    return (unsigned)__cvta_generic_to_shared(p);
}
__device__ __forceinline__ void mma16816(float* d, const unsigned* a, const unsigned* b){
    asm volatile(
        "mma.sync.aligned.m16n8k16.row.col.f32.bf16.bf16.f32 "
        "{%0,%1,%2,%3}, {%4,%5,%6,%7}, {%8,%9}, {%0,%1,%2,%3};"
        : "+f"(d[0]), "+f"(d[1]), "+f"(d[2]), "+f"(d[3])
        : "r"(a[0]), "r"(a[1]), "r"(a[2]), "r"(a[3]), "r"(b[0]), "r"(b[1]));
}
__device__ __forceinline__ void ldsm4(unsigned& r0, unsigned& r1, unsigned& r2,
                                      unsigned& r3, unsigned addr){
    asm volatile("ldmatrix.sync.aligned.m8n8.x4.shared.b16 {%0,%1,%2,%3}, [%4];"
        : "=r"(r0), "=r"(r1), "=r"(r2), "=r"(r3) : "r"(addr));
}

// -------- init --------
__global__ void k_init(const float* __restrict__ eh, const float* __restrict__ ec){
    int i = blockIdx.x*blockDim.x + threadIdx.x;
    if (i < Bb*Hh){
        int b = i >> 9, k = i & 511;
        g_hT[0][k*Bb + b] = eh[i];
        g_c[i] = ec[i];
    }
    if (i < Bb) g_mask[i] = 1.0f;
    if (i < Tt*Bb) g_amax[i] = 0ull;
    if (i == 0) g_x0nz = 0;
}

// -------- W_out 3-way bf16 split: layout [tile][kc][split][v][k32] --------
__global__ void __launch_bounds__(256) k_wsplit(const float* __restrict__ W){
    long long tid = (long long)blockIdx.x*256 + threadIdx.x;
    int v  = (int)(tid >> 6);
    int k0 = ((int)tid & 63) << 3;
    const float4* src = (const float4*)(W + (size_t)v*Hh + k0);
    float4 a = src[0], b4 = src[1];
    float w[8] = {a.x, a.y, a.z, a.w, b4.x, b4.y, b4.z, b4.w};
    unsigned p1[4], p2[4], p3[4];
    #pragma unroll
    for (int i = 0; i < 4; i++){
        unsigned lo[3], hi[3];
        #pragma unroll
        for (int half = 0; half < 2; half++){
            float x = w[2*i + half];
            __nv_bfloat16 s1 = __float2bfloat16(x);
            float r = x - __bfloat162float(s1);
            __nv_bfloat16 s2 = __float2bfloat16(r);
            float r2 = r - __bfloat162float(s2);
            __nv_bfloat16 s3 = __float2bfloat16(r2);
            unsigned* dst = half ? hi : lo;
            dst[0] = __bfloat16_as_ushort(s1);
            dst[1] = __bfloat16_as_ushort(s2);
            dst[2] = __bfloat16_as_ushort(s3);
        }
        p1[i] = lo[0] | (hi[0] << 16);
        p2[i] = lo[1] | (hi[1] << 16);
        p3[i] = lo[2] | (hi[2] << 16);
    }
    int tile = v >> 7, kc = k0 >> 5;
    char* base = (char*)g_Wsplit + ((size_t)(tile*NKC + kc)*3)*8192
               + (size_t)(v & 127)*64 + (size_t)(k0 & 31)*2;
    *(uint4*)(base        ) = make_uint4(p1[0], p1[1], p1[2], p1[3]);
    *(uint4*)(base +  8192) = make_uint4(p2[0], p2[1], p2[2], p2[3]);
    *(uint4*)(base + 16384) = make_uint4(p3[0], p3[1], p3[2], p3[3]);
}

// -------- transpose for W_hh --------
__global__ void k_transpose(const float* __restrict__ src, float* __restrict__ dst,
                            int rows, int cols){
    __shared__ float tile[32][33];
    int c0 = blockIdx.y * 32, r0 = blockIdx.x * 32;
    int x = threadIdx.x, y0 = threadIdx.y;
    #pragma unroll
    for (int y = y0; y < 32; y += 8)
        tile[y][x] = src[(size_t)(r0 + y)*cols + c0 + x];
    __syncthreads();
    #pragma unroll
    for (int y = y0; y < 32; y += 8)
        dst[(size_t)(c0 + y)*rows + r0 + x] = tile[x][y];
}

// -------- x0 zero scan --------
__global__ void k_zchk(const float* __restrict__ x0){
    int i = blockIdx.x*blockDim.x + threadIdx.x;
    int nz = 0;
    for (int v = i*4; v < Vv; v += 32768){
        float4 x = *(const float4*)(x0 + v);
        if (x.x != 0.f || x.y != 0.f || x.z != 0.f || x.w != 0.f) nz = 1;
    }
    if (__syncthreads_or(nz)) { if (threadIdx.x == 0) g_x0nz = 1; }
}

// -------- xv[j] = dot(W_ih[j,:], x0) --------
__global__ void k_xv(const float* __restrict__ W_ih, const float* __restrict__ x0){
    int j = blockIdx.x;
    if (!g_x0nz){ if (threadIdx.x == 0) g_xv[j] = 0.f; return; }
    const float* row = W_ih + (size_t)j*Vv;
    float s = 0.f;
    for (int v = threadIdx.x; v < Vv; v += 256) s += row[v]*x0[v];
    __shared__ float red[256];
    red[threadIdx.x] = s; __syncthreads();
    for (int o = 128; o > 0; o >>= 1){
        if (threadIdx.x < o) red[threadIdx.x] += red[threadIdx.x+o];
        __syncthreads();
    }
    if (threadIdx.x == 0) g_xv[j] = red[0];
}

// -------- fused gates GEMM + LSTM + h-split emit (+ t-1 finalize) --------
__global__ void __launch_bounds__(256) k_gates(
    const float* __restrict__ b_ih, const float* __restrict__ b_hh,
    const float* __restrict__ W_ih, float* __restrict__ out, int t)
{
    __shared__ float sW[2][32*64];
    __shared__ float sH[2][32*16];
    __shared__ float sG[64*17];
    int tx = threadIdx.x;
    int ht = blockIdx.x >> 2, bt = blockIdx.x & 3;
    const float* hT = g_hT[t & 1];

    int r = tx >> 2, bq = tx & 3;
    int gate = r >> 4, h_l = r & 15;
    int j = gate*512 + ht*16 + h_l;

    float xterm[4];
    if (t == 0){
        float xv = g_xv[j];
        #pragma unroll
        for (int i = 0; i < 4; i++) xterm[i] = xv;
    } else {
        #pragma unroll
        for (int i = 0; i < 4; i++){
            int b = bt*16 + bq*4 + i;
            int idx = dekey(g_amax[(t-1)*Bb + b]);
            xterm[i] = __ldg(W_ih + (size_t)j*Vv + idx);
        }
    }
    float bias = b_ih[j] + b_hh[j];

    if (t > 0 && blockIdx.x == 0 && tx < Bb){
        unsigned long long key = g_amax[(t-1)*Bb + tx];
        int idx = dekey(key);
        out[(size_t)(t-1)*Bb*Vv + (size_t)tx*Vv + idx] = 1.0f;
        out[98304000ull + (size_t)(t-1)*Bb + tx] = g_mask[tx];
        if (idx == 0) g_mask[tx] = 0.f;
    }

    int wc0 = tx*2;
    unsigned swb[2], shb[2];
    swb[0] = smem_u32(&sW[0][0]); swb[1] = smem_u32(&sW[1][0]);
    shb[0] = smem_u32(&sH[0][0]); shb[1] = smem_u32(&sH[1][0]);

    #define G_ISSUE(buf, tile) do{                                             \
        int k0_ = (tile)*32;                                                   \
        _Pragma("unroll")                                                      \
        for (int s = 0; s < 2; s++){                                           \
            int c = wc0 + s;                                                   \
            int kk = c >> 4, jq = c & 15;                                      \
            int gg_ = jq >> 2, hl_ = (jq & 3)*4;                               \
            cp16(swb[buf] + (unsigned)(kk*64 + jq*4)*4,                        \
                 g_WhhT + (size_t)(k0_+kk)*Gg + gg_*512 + ht*16 + hl_);        \
        }                                                                      \
        if (tx < 128){                                                         \
            int kk = tx >> 2, bq_ = tx & 3;                                    \
            cp16(shb[buf] + (unsigned)(kk*16 + bq_*4)*4,                       \
                 hT + (size_t)(k0_+kk)*Bb + bt*16 + bq_*4);                    \
        }                                                                      \
    } while(0)

    float acc[4] = {0.f,0.f,0.f,0.f};
    G_ISSUE(0, 0); CP_COMMIT();
    G_ISSUE(1, 1); CP_COMMIT();
    for (int i = 0; i < 16; i++){
        CP_WAIT1();
        __syncthreads();
        int buf = i & 1;
        #pragma unroll
        for (int k = 0; k < 32; k++){
            float w = sW[buf][k*64 + r];
            float4 h4 = *(const float4*)(&sH[buf][k*16 + bq*4]);
            acc[0] = fmaf(w, h4.x, acc[0]);
            acc[1] = fmaf(w, h4.y, acc[1]);
            acc[2] = fmaf(w, h4.z, acc[2]);
            acc[3] = fmaf(w, h4.w, acc[3]);
        }
        __syncthreads();
        if (i + 2 < 16) G_ISSUE(buf, i + 2);
        CP_COMMIT();
    }
    #undef G_ISSUE

    #pragma unroll
    for (int i = 0; i < 4; i++) sG[r*17 + bq*4 + i] = acc[i] + bias + xterm[i];
    __syncthreads();

    int h2 = tx & 15, b2 = tx >> 4;
    float gi = sG[( 0 + h2)*17 + b2];
    float gf = sG[(16 + h2)*17 + b2];
    float gg = sG[(32 + h2)*17 + b2];
    float go = sG[(48 + h2)*17 + b2];
    int b = bt*16 + b2, h = ht*16 + h2;
    float c  = g_c[b*Hh + h];
    float si = 1.f/(1.f+expf(-gi));
    float sf = 1.f/(1.f+expf(-gf));
    float so = 1.f/(1.f+expf(-go));
    float cn = sf*c + si*tanhf(gg);
    float hn = so*tanhf(cn);
    g_c[b*Hh + h] = cn;
    g_hT[(t + 1) & 1][h*Bb + b] = hn;

    // 3-way bf16 split of hn -> g_Hsplit[kc][split][b][k32]
    __nv_bfloat16 s1 = __float2bfloat16(hn);
    float r1 = hn - __bfloat162float(s1);
    __nv_bfloat16 s2 = __float2bfloat16(r1);
    float r2 = r1 - __bfloat162float(s2);
    __nv_bfloat16 s3 = __float2bfloat16(r2);
    int kc = h >> 5, koff = h & 31;
    size_t eb = ((size_t)(kc*3)*64 + b)*32 + koff;
    g_Hsplit[eb           ] = s1;
    g_Hsplit[eb + 64*32   ] = s2;
    g_Hsplit[eb + 2*64*32 ] = s3;
}

// -------- logits via mma.sync bf16x3 + ldmatrix fragment loads --------
// grid 250, 128 thr (4 warps). Block tile 128v x 64b, warp tile 32v x 64b.
// 48 LDSM : 192 HMMA per warp-stage (was 240 scalar LDS) -> HMMA-bound.
__global__ void __launch_bounds__(128) k_logits_mma(
    const float* __restrict__ b_out, float* __restrict__ out, int t)
{
    extern __shared__ char dyn[];
    int tx = threadIdx.x;
    int vt = blockIdx.x;
    int lane = tx & 31, warp = tx >> 5;
    int g = lane >> 2, tg = lane & 3;
    int vwarp = warp * 32;
    unsigned dynb = smem_u32(dyn);
    const char* wsrc = (const char*)g_Wsplit + (size_t)vt*NKC*WSTEP;
    const char* hsrc = (const char*)g_Hsplit;

    // ldmatrix lane address components
    int arow = lane & 15;              // A: row within 16-row tile
    int acol8 = (lane >> 4) << 3;      // A: +8 k for upper 16 lanes

    float acc[2][8][4];
    #pragma unroll
    for (int mi = 0; mi < 2; mi++)
        #pragma unroll
        for (int nb = 0; nb < 8; nb++)
            #pragma unroll
            for (int q = 0; q < 4; q++) acc[mi][nb][q] = 0.f;

    #define L_ISSUE(st_, buf_) do{                                             \
        unsigned db = dynb + (unsigned)(buf_)*STAGE;                           \
        const char* wsc = wsrc + (size_t)(st_)*WSTEP;                          \
        _Pragma("unroll")                                                      \
        for (int i_ = 0; i_ < 12; i_++){                                       \
            int idx = tx + i_*128;                                             \
            int rr = idx >> 2, kq = idx & 3;                                   \
            int sp = rr >> 7, vv = rr & 127;                                   \
            cp16(db + (unsigned)(sp*10240 + vv*PITCH + kq*16),                 \
                 wsc + (size_t)sp*8192 + vv*64 + kq*16);                       \
        }                                                                      \
        const char* hsc = hsrc + (size_t)(st_)*HSTEP;                          \
        _Pragma("unroll")                                                      \
        for (int i_ = 0; i_ < 6; i_++){                                        \
            int idx = tx + i_*128;                                             \
            int rr = idx >> 2, kq = idx & 3;                                   \
            int sp = rr >> 6, bb = rr & 63;                                    \
            cp16(db + (unsigned)(WREG + sp*5120 + bb*PITCH + kq*16),           \
                 hsc + (size_t)sp*4096 + bb*64 + kq*16);                       \
        }                                                                      \
    } while(0)

    L_ISSUE(0, 0); CP_COMMIT();
    L_ISSUE(1, 1); CP_COMMIT();

    for (int st = 0; st < NKC; st++){
        CP_WAIT1();
        __syncthreads();
        unsigned sb = dynb + (unsigned)(st & 1)*STAGE;
        #pragma unroll
        for (int ks = 0; ks < 32; ks += 16){
            #pragma unroll
            for (int pb = 0; pb < 3; pb++){
                // B fragments for all 8 n-blocks (64 b rows), loaded once per pb
                unsigned hb = sb + WREG + (unsigned)pb*5120u;
                unsigned bf[8][2];
                ldsm4(bf[0][0], bf[1][0], bf[2][0], bf[3][0],
                      hb + (unsigned)(lane*PITCH + ks*2));
                ldsm4(bf[4][0], bf[5][0], bf[6][0], bf[7][0],
                      hb + (unsigned)((32 + lane)*PITCH + ks*2));
                ldsm4(bf[0][1], bf[1][1], bf[2][1], bf[3][1],
                      hb + (unsigned)(lane*PITCH + (ks + 8)*2));
                ldsm4(bf[4][1], bf[5][1], bf[6][1], bf[7][1],
                      hb + (unsigned)((32 + lane)*PITCH + (ks + 8)*2));
                #pragma unroll
                for (int pa = 0; pa < 3; pa++){
                    if (pa >= 3 - pb) continue;   // products: i+j <= 2
                    unsigned ab = sb + (unsigned)pa*10240u;
                    unsigned aaddr = ab + (unsigned)((vwarp + arow)*PITCH + (ks + acol8)*2);
                    unsigned a0[4], a1[4];
                    ldsm4(a0[0], a0[1], a0[2], a0[3], aaddr);
                    ldsm4(a1[0], a1[1], a1[2], a1[3], aaddr + 16u*PITCH);
                    #pragma unroll
                    for (int nb = 0; nb < 8; nb++){
                        mma16816(acc[0][nb], a0, bf[nb]);
                        mma16816(acc[1][nb], a1, bf[nb]);
                    }
                }
            }
        }
        __syncthreads();
        if (st + 2 < NKC) L_ISSUE(st + 2, st & 1);
        CP_COMMIT();
    }
    #undef L_ISSUE

    // -------- epilogue: stage D in smem [b][v], coalesced out + argmax --------
    asm volatile("cp.async.wait_group 0;");
    __syncthreads();
    float* sD = (float*)dyn;
    #pragma unroll
    for (int mi = 0; mi < 2; mi++)
        #pragma unroll
        for (int nb = 0; nb < 8; nb++){
            int v0 = vwarp + mi*16 + g;
            int b0 = nb*8 + 2*tg;
            sD[(b0    )*DPITCH + v0    ] = acc[mi][nb][0];
            sD[(b0 + 1)*DPITCH + v0    ] = acc[mi][nb][1];
            sD[(b0    )*DPITCH + v0 + 8] = acc[mi][nb][2];
            sD[(b0 + 1)*DPITCH + v0 + 8] = acc[mi][nb][3];
        }
    __syncthreads();

    int vblk = vt * 128;
    size_t tbase = (size_t)t * Bb * Vv;
    float* logits = out + 49152000ull;
    float4 zero4 = make_float4(0.f, 0.f, 0.f, 0.f);
    int v4 = lane * 4;
    float4 bo = *(const float4*)(b_out + vblk + v4);
    #pragma unroll
    for (int rr = 0; rr < 16; rr++){
        int b = rr*4 + warp;
        float4 d = *(const float4*)(sD + b*DPITCH + v4);
        d.x += bo.x; d.y += bo.y; d.z += bo.z; d.w += bo.w;
        size_t o = tbase + (size_t)b*Vv + vblk + v4;
        *(float4*)(logits + o) = d;
        *(float4*)(out + o) = zero4;
        float vals[4] = {d.x, d.y, d.z, d.w};
        unsigned bk = fkey(vals[0]); int bv = v4;
        #pragma unroll
        for (int q = 1; q < 4; q++){
            unsigned kq = fkey(vals[q]);
            if (kq > bk){ bk = kq; bv = v4 + q; }
        }
        unsigned m = __reduce_max_sync(0xFFFFFFFFu, bk);
        unsigned bal = __ballot_sync(0xFFFFFFFFu, bk == m);
        int src = __ffs(bal) - 1;
        if (lane == src){
            unsigned long long key = ((unsigned long long)m << 32) |
                (unsigned long long)(0xFFFFFFFFu - (unsigned)(vblk + bv));
            atomicMax(&g_amax[(size_t)t*Bb + b], key);
        }
    }
}

// -------- trailing finalize --------
__global__ void k_final(float* __restrict__ out){
    int b = threadIdx.x;
    if (b >= Bb) return;
    unsigned long long key = g_amax[(Tt-1)*Bb + b];
    int idx = dekey(key);
    out[(size_t)(Tt-1)*Bb*Vv + (size_t)b*Vv + idx] = 1.0f;
    out[98304000ull + (size_t)(Tt-1)*Bb + b] = g_mask[b];
}

extern "C" void kernel_launch(void* const* d_in, const int* in_sizes, int n_in,
                              void* d_out, int out_size){
    const float* eh    = (const float*)d_in[0];
    const float* ec    = (const float*)d_in[1];
    const float* W_ih  = (const float*)d_in[2];
    const float* W_hh  = (const float*)d_in[3];
    const float* b_ih  = (const float*)d_in[4];
    const float* b_hh  = (const float*)d_in[5];
    const float* W_out = (const float*)d_in[6];
    const float* b_out = (const float*)d_in[7];
    const float* x0    = (const float*)d_in[8];
    float* out = (float*)d_out;

    float* WhhT; cudaGetSymbolAddress((void**)&WhhT, g_WhhT);
    cudaFuncSetAttribute(k_logits_mma, cudaFuncAttributeMaxDynamicSharedMemorySize,
                         2*STAGE);

    k_init<<<128, 256>>>(eh, ec);
    k_wsplit<<<(Vv*Hh/8)/256, 256>>>(W_out);
    {   dim3 g(Gg/32, Hh/32), b(32, 8);
        k_transpose<<<g, b>>>(W_hh, WhhT, Gg, Hh); }
    k_zchk<<<8, 1024>>>(x0);
    k_xv<<<Gg, 256>>>(W_ih, x0);
    for (int t = 0; t < Tt; t++){
        k_gates<<<128, 256>>>(b_ih, b_hh, W_ih, out, t);
        k_logits_mma<<<NVT, 128, 2*STAGE>>>(b_out, out, t);
    }
    k_final<<<1, 64>>>(out);
}

// round 14
// speedup vs baseline: 1.3597x; 1.3597x over previous
#include <cuda_runtime.h>
#include <cuda_bf16.h>
#include <cstdint>
#include <stdint.h>
#include <math.h>

#define Bb 64
#define Hh 512
#define Gg 2048
#define Vv 32000
#define Tt 24

#define NVT 250                 // v tiles of 128
#define NKC 16                  // k chunks of 32
#define WSTEP 16384             // bytes per (tile,kchunk): 2 splits x 128 v x 32 k x 2B
#define HSTEP 8192              // bytes per kchunk: 2 splits x 64 b x 32 k x 2B
#define PITCH 80                // smem row pitch bytes (32 bf16 data + 8 pad)
#define WREG  20480             // 2 * 128 * 80
#define HREG  10240             // 2 * 64 * 80
#define STAGE 30720             // WREG + HREG
#define DPITCH 132              // epilogue smem pitch (floats)

// -------- scratch (static device globals; no allocation) --------
__device__ __nv_bfloat16 g_Wsplit[(size_t)NVT*NKC*(WSTEP/2)];  // 65.5 MB
__device__ __nv_bfloat16 g_Hsplit[NKC*(HSTEP/2)];              // 131 KB
__device__ float g_WhhT[Hh*Gg];
__device__ float g_hT[2][Hh*Bb];
__device__ float g_c[Bb*Hh];
__device__ float g_xv[Gg];
__device__ unsigned long long g_amax[Tt*Bb];
__device__ float g_mask[Bb];
__device__ int   g_x0nz;

__device__ __forceinline__ unsigned fkey(float f){
    unsigned u = __float_as_uint(f);
    return (u & 0x80000000u) ? ~u : (u | 0x80000000u);
}
__device__ __forceinline__ int dekey(unsigned long long key){
    return (int)(0xFFFFFFFFu - (unsigned)(key & 0xFFFFFFFFull));
}
__device__ __forceinline__ void cp16(unsigned d, const void* s){
    asm volatile("cp.async.cg.shared.global [%0], [%1], 16;" :: "r"(d), "l"(s));
}
#define CP_COMMIT() asm volatile("cp.async.commit_group;")
#define CP_WAIT1()  asm volatile("cp.async.wait_group 1;")
__device__ __forceinline__ unsigned smem_u32(const void* p){
    return (unsigned)__cvta_generic_to_shared(p);
}
__device__ __forceinline__ void mma16816(float* d, const unsigned* a, const unsigned* b){
    asm volatile(
        "mma.sync.aligned.m16n8k16.row.col.f32.bf16.bf16.f32 "
        "{%0,%1,%2,%3}, {%4,%5,%6,%7}, {%8,%9}, {%0,%1,%2,%3};"
        : "+f"(d[0]), "+f"(d[1]), "+f"(d[2]), "+f"(d[3])
        : "r"(a[0]), "r"(a[1]), "r"(a[2]), "r"(a[3]), "r"(b[0]), "r"(b[1]));
}

// -------- init --------
__global__ void k_init(const float* __restrict__ eh, const float* __restrict__ ec){
    int i = blockIdx.x*blockDim.x + threadIdx.x;
    if (i < Bb*Hh){
        int b = i >> 9, k = i & 511;
        g_hT[0][k*Bb + b] = eh[i];
        g_c[i] = ec[i];
    }
    if (i < Bb) g_mask[i] = 1.0f;
    if (i < Tt*Bb) g_amax[i] = 0ull;
    if (i == 0) g_x0nz = 0;
}

// -------- W_out 2-way bf16 split: layout [tile][kc][split][v][k32] --------
__global__ void __launch_bounds__(256) k_wsplit(const float* __restrict__ W){
    long long tid = (long long)blockIdx.x*256 + threadIdx.x;
    int v  = (int)(tid >> 6);
    int k0 = ((int)tid & 63) << 3;
    const float4* src = (const float4*)(W + (size_t)v*Hh + k0);
    float4 a = src[0], b4 = src[1];
    float w[8] = {a.x, a.y, a.z, a.w, b4.x, b4.y, b4.z, b4.w};
    unsigned p1[4], p2[4];
    #pragma unroll
    for (int i = 0; i < 4; i++){
        unsigned lo[2], hi[2];
        #pragma unroll
        for (int half = 0; half < 2; half++){
            float x = w[2*i + half];
            __nv_bfloat16 s1 = __float2bfloat16(x);
            float r = x - __bfloat162float(s1);
            __nv_bfloat16 s2 = __float2bfloat16(r);
            unsigned* dst = half ? hi : lo;
            dst[0] = __bfloat16_as_ushort(s1);
            dst[1] = __bfloat16_as_ushort(s2);
        }
        p1[i] = lo[0] | (hi[0] << 16);
        p2[i] = lo[1] | (hi[1] << 16);
    }
    int tile = v >> 7, kc = k0 >> 5;
    char* base = (char*)g_Wsplit + ((size_t)(tile*NKC + kc)*2)*8192
               + (size_t)(v & 127)*64 + (size_t)(k0 & 31)*2;
    *(uint4*)(base        ) = make_uint4(p1[0], p1[1], p1[2], p1[3]);
    *(uint4*)(base +  8192) = make_uint4(p2[0], p2[1], p2[2], p2[3]);
}

// -------- transpose for W_hh --------
__global__ void k_transpose(const float* __restrict__ src, float* __restrict__ dst,
                            int rows, int cols){
    __shared__ float tile[32][33];
    int c0 = blockIdx.y * 32, r0 = blockIdx.x * 32;
    int x = threadIdx.x, y0 = threadIdx.y;
    #pragma unroll
    for (int y = y0; y < 32; y += 8)
        tile[y][x] = src[(size_t)(r0 + y)*cols + c0 + x];
    __syncthreads();
    #pragma unroll
    for (int y = y0; y < 32; y += 8)
        dst[(size_t)(c0 + y)*rows + r0 + x] = tile[x][y];
}

// -------- x0 zero scan --------
__global__ void k_zchk(const float* __restrict__ x0){
    int i = blockIdx.x*blockDim.x + threadIdx.x;
    int nz = 0;
    for (int v = i*4; v < Vv; v += 32768){
        float4 x = *(const float4*)(x0 + v);
        if (x.x != 0.f || x.y != 0.f || x.z != 0.f || x.w != 0.f) nz = 1;
    }
    if (__syncthreads_or(nz)) { if (threadIdx.x == 0) g_x0nz = 1; }
}

// -------- xv[j] = dot(W_ih[j,:], x0) --------
__global__ void k_xv(const float* __restrict__ W_ih, const float* __restrict__ x0){
    int j = blockIdx.x;
    if (!g_x0nz){ if (threadIdx.x == 0) g_xv[j] = 0.f; return; }
    const float* row = W_ih + (size_t)j*Vv;
    float s = 0.f;
    for (int v = threadIdx.x; v < Vv; v += 256) s += row[v]*x0[v];
    __shared__ float red[256];
    red[threadIdx.x] = s; __syncthreads();
    for (int o = 128; o > 0; o >>= 1){
        if (threadIdx.x < o) red[threadIdx.x] += red[threadIdx.x+o];
        __syncthreads();
    }
    if (threadIdx.x == 0) g_xv[j] = red[0];
}

// -------- fused gates GEMM + LSTM + h-split emit (+ t-1 finalize) --------
__global__ void __launch_bounds__(256) k_gates(
    const float* __restrict__ b_ih, const float* __restrict__ b_hh,
    const float* __restrict__ W_ih, float* __restrict__ out, int t)
{
    __shared__ float sW[2][32*64];
    __shared__ float sH[2][32*16];
    __shared__ float sG[64*17];
    int tx = threadIdx.x;
    int ht = blockIdx.x >> 2, bt = blockIdx.x & 3;
    const float* hT = g_hT[t & 1];

    int r = tx >> 2, bq = tx & 3;
    int gate = r >> 4, h_l = r & 15;
    int j = gate*512 + ht*16 + h_l;

    float xterm[4];
    if (t == 0){
        float xv = g_xv[j];
        #pragma unroll
        for (int i = 0; i < 4; i++) xterm[i] = xv;
    } else {
        #pragma unroll
        for (int i = 0; i < 4; i++){
            int b = bt*16 + bq*4 + i;
            int idx = dekey(g_amax[(t-1)*Bb + b]);
            xterm[i] = __ldg(W_ih + (size_t)j*Vv + idx);
        }
    }
    float bias = b_ih[j] + b_hh[j];

    if (t > 0 && blockIdx.x == 0 && tx < Bb){
        unsigned long long key = g_amax[(t-1)*Bb + tx];
        int idx = dekey(key);
        out[(size_t)(t-1)*Bb*Vv + (size_t)tx*Vv + idx] = 1.0f;
        out[98304000ull + (size_t)(t-1)*Bb + tx] = g_mask[tx];
        if (idx == 0) g_mask[tx] = 0.f;
    }

    int wc0 = tx*2;
    unsigned swb[2], shb[2];
    swb[0] = smem_u32(&sW[0][0]); swb[1] = smem_u32(&sW[1][0]);
    shb[0] = smem_u32(&sH[0][0]); shb[1] = smem_u32(&sH[1][0]);

    #define G_ISSUE(buf, tile) do{                                             \
        int k0_ = (tile)*32;                                                   \
        _Pragma("unroll")                                                      \
        for (int s = 0; s < 2; s++){                                           \
            int c = wc0 + s;                                                   \
            int kk = c >> 4, jq = c & 15;                                      \
            int gg_ = jq >> 2, hl_ = (jq & 3)*4;                               \
            cp16(swb[buf] + (unsigned)(kk*64 + jq*4)*4,                        \
                 g_WhhT + (size_t)(k0_+kk)*Gg + gg_*512 + ht*16 + hl_);        \
        }                                                                      \
        if (tx < 128){                                                         \
            int kk = tx >> 2, bq_ = tx & 3;                                    \
            cp16(shb[buf] + (unsigned)(kk*16 + bq_*4)*4,                       \
                 hT + (size_t)(k0_+kk)*Bb + bt*16 + bq_*4);                    \
        }                                                                      \
    } while(0)

    float acc[4] = {0.f,0.f,0.f,0.f};
    G_ISSUE(0, 0); CP_COMMIT();
    G_ISSUE(1, 1); CP_COMMIT();
    for (int i = 0; i < 16; i++){
        CP_WAIT1();
        __syncthreads();
        int buf = i & 1;
        #pragma unroll
        for (int k = 0; k < 32; k++){
            float w = sW[buf][k*64 + r];
            float4 h4 = *(const float4*)(&sH[buf][k*16 + bq*4]);
            acc[0] = fmaf(w, h4.x, acc[0]);
            acc[1] = fmaf(w, h4.y, acc[1]);
            acc[2] = fmaf(w, h4.z, acc[2]);
            acc[3] = fmaf(w, h4.w, acc[3]);
        }
        __syncthreads();
        if (i + 2 < 16) G_ISSUE(buf, i + 2);
        CP_COMMIT();
    }
    #undef G_ISSUE

    #pragma unroll
    for (int i = 0; i < 4; i++) sG[r*17 + bq*4 + i] = acc[i] + bias + xterm[i];
    __syncthreads();

    int h2 = tx & 15, b2 = tx >> 4;
    float gi = sG[( 0 + h2)*17 + b2];
    float gf = sG[(16 + h2)*17 + b2];
    float gg = sG[(32 + h2)*17 + b2];
    float go = sG[(48 + h2)*17 + b2];
    int b = bt*16 + b2, h = ht*16 + h2;
    float c  = g_c[b*Hh + h];
    float si = 1.f/(1.f+expf(-gi));
    float sf = 1.f/(1.f+expf(-gf));
    float so = 1.f/(1.f+expf(-go));
    float cn = sf*c + si*tanhf(gg);
    float hn = so*tanhf(cn);
    g_c[b*Hh + h] = cn;
    g_hT[(t + 1) & 1][h*Bb + b] = hn;

    // 2-way bf16 split of hn -> g_Hsplit[kc][split][b][k32]
    __nv_bfloat16 s1 = __float2bfloat16(hn);
    float r1 = hn - __bfloat162float(s1);
    __nv_bfloat16 s2 = __float2bfloat16(r1);
    int kc = h >> 5, koff = h & 31;
    size_t eb = ((size_t)(kc*2)*64 + b)*32 + koff;
    g_Hsplit[eb        ] = s1;
    g_Hsplit[eb + 2048 ] = s2;
}

// -------- logits via mma.sync bf16x2 x bf16x2 (4 products) --------
// grid 250, 128 thr (4 warps). Block tile 128v x 64b, warp tile 32v x 64b.
// R11's proven scalar-LDS mainloop, A-fragments hoisted per ks:
// per warp-stage: 96 LDS : 128 HMMA.
__global__ void __launch_bounds__(128) k_logits_mma(
    const float* __restrict__ b_out, float* __restrict__ out, int t)
{
    extern __shared__ char dyn[];
    int tx = threadIdx.x;
    int vt = blockIdx.x;
    int lane = tx & 31, warp = tx >> 5;
    int g = lane >> 2, tg = lane & 3;
    int vwarp = warp * 32;
    unsigned dynb = smem_u32(dyn);
    const char* wsrc = (const char*)g_Wsplit + (size_t)vt*NKC*WSTEP;
    const char* hsrc = (const char*)g_Hsplit;

    float acc[2][8][4];
    #pragma unroll
    for (int mi = 0; mi < 2; mi++)
        #pragma unroll
        for (int nb = 0; nb < 8; nb++)
            #pragma unroll
            for (int q = 0; q < 4; q++) acc[mi][nb][q] = 0.f;

    #define L_ISSUE(st_, buf_) do{                                             \
        unsigned db = dynb + (unsigned)(buf_)*STAGE;                           \
        const char* wsc = wsrc + (size_t)(st_)*WSTEP;                          \
        _Pragma("unroll")                                                      \
        for (int i_ = 0; i_ < 8; i_++){                                        \
            int idx = tx + i_*128;                                             \
            int rr = idx >> 2, kq = idx & 3;                                   \
            int sp = rr >> 7, vv = rr & 127;                                   \
            cp16(db + (unsigned)(sp*10240 + vv*PITCH + kq*16),                 \
                 wsc + (size_t)sp*8192 + vv*64 + kq*16);                       \
        }                                                                      \
        const char* hsc = hsrc + (size_t)(st_)*HSTEP;                          \
        _Pragma("unroll")                                                      \
        for (int i_ = 0; i_ < 4; i_++){                                        \
            int idx = tx + i_*128;                                             \
            int rr = idx >> 2, kq = idx & 3;                                   \
            int sp = rr >> 6, bb = rr & 63;                                    \
            cp16(db + (unsigned)(WREG + sp*5120 + bb*PITCH + kq*16),           \
                 hsc + (size_t)sp*4096 + bb*64 + kq*16);                       \
        }                                                                      \
    } while(0)

    L_ISSUE(0, 0); CP_COMMIT();
    L_ISSUE(1, 1); CP_COMMIT();

    for (int st = 0; st < NKC; st++){
        CP_WAIT1();
        __syncthreads();
        const char* sb = dyn + (st & 1)*STAGE;
        #pragma unroll
        for (int ks = 0; ks < 32; ks += 16){
            // A fragments for both splits, hoisted (reused across both pb)
            unsigned a[2][2][4];   // [pa][mi][4]
            #pragma unroll
            for (int pa = 0; pa < 2; pa++){
                const char* ab = sb + pa*10240;
                #pragma unroll
                for (int mi = 0; mi < 2; mi++){
                    int row = vwarp + mi*16 + g;
                    a[pa][mi][0] = *(const unsigned*)(ab + (row    )*PITCH + (ks + 2*tg    )*2);
                    a[pa][mi][1] = *(const unsigned*)(ab + (row + 8)*PITCH + (ks + 2*tg    )*2);
                    a[pa][mi][2] = *(const unsigned*)(ab + (row    )*PITCH + (ks + 2*tg + 8)*2);
                    a[pa][mi][3] = *(const unsigned*)(ab + (row + 8)*PITCH + (ks + 2*tg + 8)*2);
                }
            }
            #pragma unroll
            for (int pb = 0; pb < 2; pb++){
                const char* hb = sb + WREG + pb*5120;
                unsigned bf[8][2];
                #pragma unroll
                for (int nb = 0; nb < 8; nb++){
                    int brow = nb*8 + g;
                    bf[nb][0] = *(const unsigned*)(hb + brow*PITCH + (ks + 2*tg    )*2);
                    bf[nb][1] = *(const unsigned*)(hb + brow*PITCH + (ks + 2*tg + 8)*2);
                }
                #pragma unroll
                for (int pa = 0; pa < 2; pa++)
                    #pragma unroll
                    for (int nb = 0; nb < 8; nb++){
                        mma16816(acc[0][nb], a[pa][0], bf[nb]);
                        mma16816(acc[1][nb], a[pa][1], bf[nb]);
                    }
            }
        }
        __syncthreads();
        if (st + 2 < NKC) L_ISSUE(st + 2, st & 1);
        CP_COMMIT();
    }
    #undef L_ISSUE

    // -------- epilogue: stage D in smem [b][v], coalesced out + argmax --------
    asm volatile("cp.async.wait_group 0;");
    __syncthreads();
    float* sD = (float*)dyn;
    #pragma unroll
    for (int mi = 0; mi < 2; mi++)
        #pragma unroll
        for (int nb = 0; nb < 8; nb++){
            int v0 = vwarp + mi*16 + g;
            int b0 = nb*8 + 2*tg;
            sD[(b0    )*DPITCH + v0    ] = acc[mi][nb][0];
            sD[(b0 + 1)*DPITCH + v0    ] = acc[mi][nb][1];
            sD[(b0    )*DPITCH + v0 + 8] = acc[mi][nb][2];
            sD[(b0 + 1)*DPITCH + v0 + 8] = acc[mi][nb][3];
        }
    __syncthreads();

    int vblk = vt * 128;
    size_t tbase = (size_t)t * Bb * Vv;
    float* logits = out + 49152000ull;
    float4 zero4 = make_float4(0.f, 0.f, 0.f, 0.f);
    int v4 = lane * 4;
    float4 bo = *(const float4*)(b_out + vblk + v4);
    #pragma unroll
    for (int rr = 0; rr < 16; rr++){
        int b = rr*4 + warp;
        float4 d = *(const float4*)(sD + b*DPITCH + v4);
        d.x += bo.x; d.y += bo.y; d.z += bo.z; d.w += bo.w;
        size_t o = tbase + (size_t)b*Vv + vblk + v4;
        *(float4*)(logits + o) = d;
        *(float4*)(out + o) = zero4;
        float vals[4] = {d.x, d.y, d.z, d.w};
        unsigned bk = fkey(vals[0]); int bv = v4;
        #pragma unroll
        for (int q = 1; q < 4; q++){
            unsigned kq = fkey(vals[q]);
            if (kq > bk){ bk = kq; bv = v4 + q; }
        }
        unsigned m = __reduce_max_sync(0xFFFFFFFFu, bk);
        unsigned bal = __ballot_sync(0xFFFFFFFFu, bk == m);
        int src = __ffs(bal) - 1;
        if (lane == src){
            unsigned long long key = ((unsigned long long)m << 32) |
                (unsigned long long)(0xFFFFFFFFu - (unsigned)(vblk + bv));
            atomicMax(&g_amax[(size_t)t*Bb + b], key);
        }
    }
}

// -------- trailing finalize --------
__global__ void k_final(float* __restrict__ out){
    int b = threadIdx.x;
    if (b >= Bb) return;
    unsigned long long key = g_amax[(Tt-1)*Bb + b];
    int idx = dekey(key);
    out[(size_t)(Tt-1)*Bb*Vv + (size_t)b*Vv + idx] = 1.0f;
    out[98304000ull + (size_t)(Tt-1)*Bb + b] = g_mask[b];
}

extern "C" void kernel_launch(void* const* d_in, const int* in_sizes, int n_in,
                              void* d_out, int out_size){
    const float* eh    = (const float*)d_in[0];
    const float* ec    = (const float*)d_in[1];
    const float* W_ih  = (const float*)d_in[2];
    const float* W_hh  = (const float*)d_in[3];
    const float* b_ih  = (const float*)d_in[4];
    const float* b_hh  = (const float*)d_in[5];
    const float* W_out = (const float*)d_in[6];
    const float* b_out = (const float*)d_in[7];
    const float* x0    = (const float*)d_in[8];
    float* out = (float*)d_out;

    float* WhhT; cudaGetSymbolAddress((void**)&WhhT, g_WhhT);
    cudaFuncSetAttribute(k_logits_mma, cudaFuncAttributeMaxDynamicSharedMemorySize,
                         2*STAGE);

    k_init<<<128, 256>>>(eh, ec);
    k_wsplit<<<(Vv*Hh/8)/256, 256>>>(W_out);
    {   dim3 g(Gg/32, Hh/32), b(32, 8);
        k_transpose<<<g, b>>>(W_hh, WhhT, Gg, Hh); }
    k_zchk<<<8, 1024>>>(x0);
    k_xv<<<Gg, 256>>>(W_ih, x0);
    for (int t = 0; t < Tt; t++){
        k_gates<<<128, 256>>>(b_ih, b_hh, W_ih, out, t);
        k_logits_mma<<<NVT, 128, 2*STAGE>>>(b_out, out, t);
    }
    k_final<<<1, 64>>>(out);
}

// round 16
// speedup vs baseline: 1.4381x; 1.0577x over previous
#include <cuda_runtime.h>
#include <cuda_bf16.h>
#include <cstdint>
#include <stdint.h>
#include <math.h>

#define Bb 64
#define Hh 512
#define Gg 2048
#define Vv 32000
#define Tt 24

#define NVT 250                 // v tiles of 128
#define NKC 16                  // k chunks of 32
#define WSTEP 16384             // bytes per (tile,kchunk): 2 splits x 128 v x 32 k x 2B
#define HSTEP 8192              // bytes per kchunk: 2 splits x 64 b x 32 k x 2B
#define PITCH 80                // smem row pitch bytes (32 bf16 data + 8 pad)
#define WREG  20480             // 2 * 128 * 80
#define HREG  10240             // 2 * 64 * 80
#define STAGE 30720             // WREG + HREG
#define DPITCH 132              // epilogue smem pitch (floats)

// -------- scratch (static device globals; no allocation) --------
__device__ __nv_bfloat16 g_Wsplit[(size_t)NVT*NKC*(WSTEP/2)];  // 65.5 MB
__device__ __nv_bfloat16 g_Hsplit[NKC*(HSTEP/2)];              // 131 KB
__device__ float g_WhhT[Hh*Gg];
__device__ float g_hT[2][Hh*Bb];
__device__ float g_c[Bb*Hh];
__device__ float g_xv[Gg];
__device__ unsigned long long g_amax[Tt*Bb];
__device__ float g_mask[Bb];
__device__ int   g_x0nz;

__device__ __forceinline__ unsigned fkey(float f){
    unsigned u = __float_as_uint(f);
    return (u & 0x80000000u) ? ~u : (u | 0x80000000u);
}
__device__ __forceinline__ int dekey(unsigned long long key){
    return (int)(0xFFFFFFFFu - (unsigned)(key & 0xFFFFFFFFull));
}
__device__ __forceinline__ void cp16(unsigned d, const void* s){
    asm volatile("cp.async.cg.shared.global [%0], [%1], 16;" :: "r"(d), "l"(s));
}
#define CP_COMMIT() asm volatile("cp.async.commit_group;")
#define CP_WAIT1()  asm volatile("cp.async.wait_group 1;")
__device__ __forceinline__ unsigned smem_u32(const void* p){
    return (unsigned)__cvta_generic_to_shared(p);
}
__device__ __forceinline__ void mma16816(float* d, const unsigned* a, const unsigned* b){
    asm volatile(
        "mma.sync.aligned.m16n8k16.row.col.f32.bf16.bf16.f32 "
        "{%0,%1,%2,%3}, {%4,%5,%6,%7}, {%8,%9}, {%0,%1,%2,%3};"
        : "+f"(d[0]), "+f"(d[1]), "+f"(d[2]), "+f"(d[3])
        : "r"(a[0]), "r"(a[1]), "r"(a[2]), "r"(a[3]), "r"(b[0]), "r"(b[1]));
}
// streaming stores (evict-first): keep L2 for the W-split working set
__device__ __forceinline__ void stcs4(float* p, float4 v){
    asm volatile("st.global.cs.v4.f32 [%0], {%1,%2,%3,%4};"
        :: "l"(p), "f"(v.x), "f"(v.y), "f"(v.z), "f"(v.w) : "memory");
}

// -------- init --------
__global__ void k_init(const float* __restrict__ eh, const float* __restrict__ ec){
    int i = blockIdx.x*blockDim.x + threadIdx.x;
    if (i < Bb*Hh){
        int b = i >> 9, k = i & 511;
        g_hT[0][k*Bb + b] = eh[i];
        g_c[i] = ec[i];
    }
    if (i < Bb) g_mask[i] = 1.0f;
    if (i < Tt*Bb) g_amax[i] = 0ull;
    if (i == 0) g_x0nz = 0;
}

// -------- W_out 2-way bf16 split: layout [tile][kc][split][v][k32] --------
__global__ void __launch_bounds__(256) k_wsplit(const float* __restrict__ W){
    long long tid = (long long)blockIdx.x*256 + threadIdx.x;
    int v  = (int)(tid >> 6);
    int k0 = ((int)tid & 63) << 3;
    const float4* src = (const float4*)(W + (size_t)v*Hh + k0);
    float4 a = src[0], b4 = src[1];
    float w[8] = {a.x, a.y, a.z, a.w, b4.x, b4.y, b4.z, b4.w};
    unsigned p1[4], p2[4];
    #pragma unroll
    for (int i = 0; i < 4; i++){
        unsigned lo[2], hi[2];
        #pragma unroll
        for (int half = 0; half < 2; half++){
            float x = w[2*i + half];
            __nv_bfloat16 s1 = __float2bfloat16(x);
            float r = x - __bfloat162float(s1);
            __nv_bfloat16 s2 = __float2bfloat16(r);
            unsigned* dst = half ? hi : lo;
            dst[0] = __bfloat16_as_ushort(s1);
            dst[1] = __bfloat16_as_ushort(s2);
        }
        p1[i] = lo[0] | (hi[0] << 16);
        p2[i] = lo[1] | (hi[1] << 16);
    }
    int tile = v >> 7, kc = k0 >> 5;
    char* base = (char*)g_Wsplit + ((size_t)(tile*NKC + kc)*2)*8192
               + (size_t)(v & 127)*64 + (size_t)(k0 & 31)*2;
    *(uint4*)(base        ) = make_uint4(p1[0], p1[1], p1[2], p1[3]);
    *(uint4*)(base +  8192) = make_uint4(p2[0], p2[1], p2[2], p2[3]);
}

// -------- transpose for W_hh --------
__global__ void k_transpose(const float* __restrict__ src, float* __restrict__ dst,
                            int rows, int cols){
    __shared__ float tile[32][33];
    int c0 = blockIdx.y * 32, r0 = blockIdx.x * 32;
    int x = threadIdx.x, y0 = threadIdx.y;
    #pragma unroll
    for (int y = y0; y < 32; y += 8)
        tile[y][x] = src[(size_t)(r0 + y)*cols + c0 + x];
    __syncthreads();
    #pragma unroll
    for (int y = y0; y < 32; y += 8)
        dst[(size_t)(c0 + y)*rows + r0 + x] = tile[x][y];
}

// -------- x0 zero scan --------
__global__ void k_zchk(const float* __restrict__ x0){
    int i = blockIdx.x*blockDim.x + threadIdx.x;
    int nz = 0;
    for (int v = i*4; v < Vv; v += 32768){
        float4 x = *(const float4*)(x0 + v);
        if (x.x != 0.f || x.y != 0.f || x.z != 0.f || x.w != 0.f) nz = 1;
    }
    if (__syncthreads_or(nz)) { if (threadIdx.x == 0) g_x0nz = 1; }
}

// -------- xv[j] = dot(W_ih[j,:], x0) --------
__global__ void k_xv(const float* __restrict__ W_ih, const float* __restrict__ x0){
    int j = blockIdx.x;
    if (!g_x0nz){ if (threadIdx.x == 0) g_xv[j] = 0.f; return; }
    const float* row = W_ih + (size_t)j*Vv;
    float s = 0.f;
    for (int v = threadIdx.x; v < Vv; v += 256) s += row[v]*x0[v];
    __shared__ float red[256];
    red[threadIdx.x] = s; __syncthreads();
    for (int o = 128; o > 0; o >>= 1){
        if (threadIdx.x < o) red[threadIdx.x] += red[threadIdx.x+o];
        __syncthreads();
    }
    if (threadIdx.x == 0) g_xv[j] = red[0];
}

// -------- fused gates GEMM + LSTM + h-split emit (+ t-1 finalize) --------
__global__ void __launch_bounds__(256) k_gates(
    const float* __restrict__ b_ih, const float* __restrict__ b_hh,
    const float* __restrict__ W_ih, float* __restrict__ out, int t)
{
    __shared__ float sW[2][32*64];
    __shared__ float sH[2][32*16];
    __shared__ float sG[64*17];
    int tx = threadIdx.x;
    int ht = blockIdx.x >> 2, bt = blockIdx.x & 3;
    const float* hT = g_hT[t & 1];

    int r = tx >> 2, bq = tx & 3;
    int gate = r >> 4, h_l = r & 15;
    int j = gate*512 + ht*16 + h_l;

    float xterm[4];
    if (t == 0){
        float xv = g_xv[j];
        #pragma unroll
        for (int i = 0; i < 4; i++) xterm[i] = xv;
    } else {
        #pragma unroll
        for (int i = 0; i < 4; i++){
            int b = bt*16 + bq*4 + i;
            int idx = dekey(g_amax[(t-1)*Bb + b]);
            xterm[i] = __ldg(W_ih + (size_t)j*Vv + idx);
        }
    }
    float bias = b_ih[j] + b_hh[j];

    if (t > 0 && blockIdx.x == 0 && tx < Bb){
        unsigned long long key = g_amax[(t-1)*Bb + tx];
        int idx = dekey(key);
        out[(size_t)(t-1)*Bb*Vv + (size_t)tx*Vv + idx] = 1.0f;
        out[98304000ull + (size_t)(t-1)*Bb + tx] = g_mask[tx];
        if (idx == 0) g_mask[tx] = 0.f;
    }

    int wc0 = tx*2;
    unsigned swb[2], shb[2];
    swb[0] = smem_u32(&sW[0][0]); swb[1] = smem_u32(&sW[1][0]);
    shb[0] = smem_u32(&sH[0][0]); shb[1] = smem_u32(&sH[1][0]);

    #define G_ISSUE(buf, tile) do{                                             \
        int k0_ = (tile)*32;                                                   \
        _Pragma("unroll")                                                      \
        for (int s = 0; s < 2; s++){                                           \
            int c = wc0 + s;                                                   \
            int kk = c >> 4, jq = c & 15;                                      \
            int gg_ = jq >> 2, hl_ = (jq & 3)*4;                               \
            cp16(swb[buf] + (unsigned)(kk*64 + jq*4)*4,                        \
                 g_WhhT + (size_t)(k0_+kk)*Gg + gg_*512 + ht*16 + hl_);        \
        }                                                                      \
        if (tx < 128){                                                         \
            int kk = tx >> 2, bq_ = tx & 3;                                    \
            cp16(shb[buf] + (unsigned)(kk*16 + bq_*4)*4,                       \
                 hT + (size_t)(k0_+kk)*Bb + bt*16 + bq_*4);                    \
        }                                                                      \
    } while(0)

    float acc[4] = {0.f,0.f,0.f,0.f};
    G_ISSUE(0, 0); CP_COMMIT();
    G_ISSUE(1, 1); CP_COMMIT();
    for (int i = 0; i < 16; i++){
        CP_WAIT1();
        __syncthreads();
        int buf = i & 1;
        #pragma unroll
        for (int k = 0; k < 32; k++){
            float w = sW[buf][k*64 + r];
            float4 h4 = *(const float4*)(&sH[buf][k*16 + bq*4]);
            acc[0] = fmaf(w, h4.x, acc[0]);
            acc[1] = fmaf(w, h4.y, acc[1]);
            acc[2] = fmaf(w, h4.z, acc[2]);
            acc[3] = fmaf(w, h4.w, acc[3]);
        }
        __syncthreads();
        if (i + 2 < 16) G_ISSUE(buf, i + 2);
        CP_COMMIT();
    }
    #undef G_ISSUE

    #pragma unroll
    for (int i = 0; i < 4; i++) sG[r*17 + bq*4 + i] = acc[i] + bias + xterm[i];
    __syncthreads();

    int h2 = tx & 15, b2 = tx >> 4;
    float gi = sG[( 0 + h2)*17 + b2];
    float gf = sG[(16 + h2)*17 + b2];
    float gg = sG[(32 + h2)*17 + b2];
    float go = sG[(48 + h2)*17 + b2];
    int b = bt*16 + b2, h = ht*16 + h2;
    float c  = g_c[b*Hh + h];
    float si = 1.f/(1.f+expf(-gi));
    float sf = 1.f/(1.f+expf(-gf));
    float so = 1.f/(1.f+expf(-go));
    float cn = sf*c + si*tanhf(gg);
    float hn = so*tanhf(cn);
    g_c[b*Hh + h] = cn;
    g_hT[(t + 1) & 1][h*Bb + b] = hn;

    // 2-way bf16 split of hn -> g_Hsplit[kc][split][b][k32]
    __nv_bfloat16 s1 = __float2bfloat16(hn);
    float r1 = hn - __bfloat162float(s1);
    __nv_bfloat16 s2 = __float2bfloat16(r1);
    int kc = h >> 5, koff = h & 31;
    size_t eb = ((size_t)(kc*2)*64 + b)*32 + koff;
    g_Hsplit[eb        ] = s1;
    g_Hsplit[eb + 2048 ] = s2;
}

// -------- logits via mma.sync bf16x2 (3 products: W1h1, W1h2, W2h1) --------
// grid 250, 128 thr (4 warps). Block tile 128v x 64b, warp tile 32v x 64b.
// W2h2 omitted: residual ~2^-32 |Wh|, negligible vs split residual 2^-16^2.
// Streaming output stores (.cs) keep the 65.5 MB W-split table L2-resident
// across all 24 steps.
__global__ void __launch_bounds__(128) k_logits_mma(
    const float* __restrict__ b_out, float* __restrict__ out, int t)
{
    extern __shared__ char dyn[];
    int tx = threadIdx.x;
    int vt = blockIdx.x;
    int lane = tx & 31, warp = tx >> 5;
    int g = lane >> 2, tg = lane & 3;
    int vwarp = warp * 32;
    unsigned dynb = smem_u32(dyn);
    const char* wsrc = (const char*)g_Wsplit + (size_t)vt*NKC*WSTEP;
    const char* hsrc = (const char*)g_Hsplit;

    float acc[2][8][4];
    #pragma unroll
    for (int mi = 0; mi < 2; mi++)
        #pragma unroll
        for (int nb = 0; nb < 8; nb++)
            #pragma unroll
            for (int q = 0; q < 4; q++) acc[mi][nb][q] = 0.f;

    #define L_ISSUE(st_, buf_) do{                                             \
        unsigned db = dynb + (unsigned)(buf_)*STAGE;                           \
        const char* wsc = wsrc + (size_t)(st_)*WSTEP;                          \
        _Pragma("unroll")                                                      \
        for (int i_ = 0; i_ < 8; i_++){                                        \
            int idx = tx + i_*128;                                             \
            int rr = idx >> 2, kq = idx & 3;                                   \
            int sp = rr >> 7, vv = rr & 127;                                   \
            cp16(db + (unsigned)(sp*10240 + vv*PITCH + kq*16),                 \
                 wsc + (size_t)sp*8192 + vv*64 + kq*16);                       \
        }                                                                      \
        const char* hsc = hsrc + (size_t)(st_)*HSTEP;                          \
        _Pragma("unroll")                                                      \
        for (int i_ = 0; i_ < 4; i_++){                                        \
            int idx = tx + i_*128;                                             \
            int rr = idx >> 2, kq = idx & 3;                                   \
            int sp = rr >> 6, bb = rr & 63;                                    \
            cp16(db + (unsigned)(WREG + sp*5120 + bb*PITCH + kq*16),           \
                 hsc + (size_t)sp*4096 + bb*64 + kq*16);                       \
        }                                                                      \
    } while(0)

    L_ISSUE(0, 0); CP_COMMIT();
    L_ISSUE(1, 1); CP_COMMIT();

    for (int st = 0; st < NKC; st++){
        CP_WAIT1();
        __syncthreads();
        const char* sb = dyn + (st & 1)*STAGE;
        #pragma unroll
        for (int ks = 0; ks < 32; ks += 16){
            // A fragments for both splits, hoisted
            unsigned a[2][2][4];   // [pa][mi][4]
            #pragma unroll
            for (int pa = 0; pa < 2; pa++){
                const char* ab = sb + pa*10240;
                #pragma unroll
                for (int mi = 0; mi < 2; mi++){
                    int row = vwarp + mi*16 + g;
                    a[pa][mi][0] = *(const unsigned*)(ab + (row    )*PITCH + (ks + 2*tg    )*2);
                    a[pa][mi][1] = *(const unsigned*)(ab + (row + 8)*PITCH + (ks + 2*tg    )*2);
                    a[pa][mi][2] = *(const unsigned*)(ab + (row    )*PITCH + (ks + 2*tg + 8)*2);
                    a[pa][mi][3] = *(const unsigned*)(ab + (row + 8)*PITCH + (ks + 2*tg + 8)*2);
                }
            }
            // pb = 0 (h1): both W splits
            {
                const char* hb = sb + WREG;
                unsigned bf[8][2];
                #pragma unroll
                for (int nb = 0; nb < 8; nb++){
                    int brow = nb*8 + g;
                    bf[nb][0] = *(const unsigned*)(hb + brow*PITCH + (ks + 2*tg    )*2);
                    bf[nb][1] = *(const unsigned*)(hb + brow*PITCH + (ks + 2*tg + 8)*2);
                }
                #pragma unroll
                for (int pa = 0; pa < 2; pa++)
                    #pragma unroll
                    for (int nb = 0; nb < 8; nb++){
                        mma16816(acc[0][nb], a[pa][0], bf[nb]);
                        mma16816(acc[1][nb], a[pa][1], bf[nb]);
                    }
            }
            // pb = 1 (h2): W1 only (W2h2 dropped)
            {
                const char* hb = sb + WREG + 5120;
                unsigned bf[8][2];
                #pragma unroll
                for (int nb = 0; nb < 8; nb++){
                    int brow = nb*8 + g;
                    bf[nb][0] = *(const unsigned*)(hb + brow*PITCH + (ks + 2*tg    )*2);
                    bf[nb][1] = *(const unsigned*)(hb + brow*PITCH + (ks + 2*tg + 8)*2);
                }
                #pragma unroll
                for (int nb = 0; nb < 8; nb++){
                    mma16816(acc[0][nb], a[0][0], bf[nb]);
                    mma16816(acc[1][nb], a[0][1], bf[nb]);
                }
            }
        }
        __syncthreads();
        if (st + 2 < NKC) L_ISSUE(st + 2, st & 1);
        CP_COMMIT();
    }
    #undef L_ISSUE

    // -------- epilogue: stage D in smem [b][v], coalesced out + argmax --------
    asm volatile("cp.async.wait_group 0;");
    __syncthreads();
    float* sD = (float*)dyn;
    #pragma unroll
    for (int mi = 0; mi < 2; mi++)
        #pragma unroll
        for (int nb = 0; nb < 8; nb++){
            int v0 = vwarp + mi*16 + g;
            int b0 = nb*8 + 2*tg;
            sD[(b0    )*DPITCH + v0    ] = acc[mi][nb][0];
            sD[(b0 + 1)*DPITCH + v0    ] = acc[mi][nb][1];
            sD[(b0    )*DPITCH + v0 + 8] = acc[mi][nb][2];
            sD[(b0 + 1)*DPITCH + v0 + 8] = acc[mi][nb][3];
        }
    __syncthreads();

    int vblk = vt * 128;
    size_t tbase = (size_t)t * Bb * Vv;
    float* logits = out + 49152000ull;
    float4 zero4 = make_float4(0.f, 0.f, 0.f, 0.f);
    int v4 = lane * 4;
    float4 bo = *(const float4*)(b_out + vblk + v4);
    #pragma unroll
    for (int rr = 0; rr < 16; rr++){
        int b = rr*4 + warp;
        float4 d = *(const float4*)(sD + b*DPITCH + v4);
        d.x += bo.x; d.y += bo.y; d.z += bo.z; d.w += bo.w;
        size_t o = tbase + (size_t)b*Vv + vblk + v4;
        stcs4(logits + o, d);
        stcs4(out + o, zero4);
        float vals[4] = {d.x, d.y, d.z, d.w};
        unsigned bk = fkey(vals[0]); int bv = v4;
        #pragma unroll
        for (int q = 1; q < 4; q++){
            unsigned kq = fkey(vals[q]);
            if (kq > bk){ bk = kq; bv = v4 + q; }
        }
        unsigned m = __reduce_max_sync(0xFFFFFFFFu, bk);
        unsigned bal = __ballot_sync(0xFFFFFFFFu, bk == m);
        int src = __ffs(bal) - 1;
        if (lane == src){
            unsigned long long key = ((unsigned long long)m << 32) |
                (unsigned long long)(0xFFFFFFFFu - (unsigned)(vblk + bv));
            atomicMax(&g_amax[(size_t)t*Bb + b], key);
        }
    }
}

// -------- trailing finalize --------
__global__ void k_final(float* __restrict__ out){
    int b = threadIdx.x;
    if (b >= Bb) return;
    unsigned long long key = g_amax[(Tt-1)*Bb + b];
    int idx = dekey(key);
    out[(size_t)(Tt-1)*Bb*Vv + (size_t)b*Vv + idx] = 1.0f;
    out[98304000ull + (size_t)(Tt-1)*Bb + b] = g_mask[b];
}

extern "C" void kernel_launch(void* const* d_in, const int* in_sizes, int n_in,
                              void* d_out, int out_size){
    const float* eh    = (const float*)d_in[0];
    const float* ec    = (const float*)d_in[1];
    const float* W_ih  = (const float*)d_in[2];
    const float* W_hh  = (const float*)d_in[3];
    const float* b_ih  = (const float*)d_in[4];
    const float* b_hh  = (const float*)d_in[5];
    const float* W_out = (const float*)d_in[6];
    const float* b_out = (const float*)d_in[7];
    const float* x0    = (const float*)d_in[8];
    float* out = (float*)d_out;

    float* WhhT; cudaGetSymbolAddress((void**)&WhhT, g_WhhT);
    cudaFuncSetAttribute(k_logits_mma, cudaFuncAttributeMaxDynamicSharedMemorySize,
                         2*STAGE);

    k_init<<<128, 256>>>(eh, ec);
    k_wsplit<<<(Vv*Hh/8)/256, 256>>>(W_out);
    {   dim3 g(Gg/32, Hh/32), b(32, 8);
        k_transpose<<<g, b>>>(W_hh, WhhT, Gg, Hh); }
    k_zchk<<<8, 1024>>>(x0);
    k_xv<<<Gg, 256>>>(W_ih, x0);
    for (int t = 0; t < Tt; t++){
        k_gates<<<128, 256>>>(b_ih, b_hh, W_ih, out, t);
        k_logits_mma<<<NVT, 128, 2*STAGE>>>(b_out, out, t);
    }
    k_final<<<1, 64>>>(out);
}